// round 6
// baseline (speedup 1.0000x reference)
#include <cuda_runtime.h>
#include <cuda_bf16.h>
#include <cstdint>

// SparseBMM: y[b,m,n] = sum_k A_masked[b,m,k] * B[b,k,n], fp32 [8,2048,2048].
// A_masked zeroes 64x64 tiles of A whose max-abs <= 1e-6.
// bf16 mma.sync m16n8k16, hi/lo split (3 products), fp32 accumulate.
// R6: fused prescan+convA; GEMM BK=64, 2 stages, 32 barriers.

#define BATCH 8
#define MDIM 2048
#define NDIM 2048
#define KDIM 2048

#define BM 256
#define BN 128
#define BK 64
#define NK (KDIM / BK)          // 32

#define A_SPLIT_BYTES 32768     // 256 rows x 64 bf16 = 256x128B
#define B_SPLIT_BYTES 16384     // 64 rows x 128 bf16 = 64x256B
#define STAGE_BYTES (2 * A_SPLIT_BYTES + 2 * B_SPLIT_BYTES)   // 98304
#define SMEM_TOTAL (2 * STAGE_BYTES)                          // 196608

__device__ __nv_bfloat16 g_Ah[(size_t)BATCH * MDIM * KDIM];
__device__ __nv_bfloat16 g_Al[(size_t)BATCH * MDIM * KDIM];
__device__ __nv_bfloat16 g_Bh[(size_t)BATCH * KDIM * NDIM];
__device__ __nv_bfloat16 g_Bl[(size_t)BATCH * KDIM * NDIM];

// ---------------- helpers ----------------
__device__ __forceinline__ uint32_t smem_u32(const void* p) {
    uint32_t a;
    asm("{ .reg .u64 t; cvta.to.shared.u64 t, %1; cvt.u32.u64 %0, t; }" : "=r"(a) : "l"(p));
    return a;
}
__device__ __forceinline__ void cpa16(uint32_t dst, const void* src) {
    asm volatile("cp.async.cg.shared.global [%0], [%1], 16;" :: "r"(dst), "l"(src));
}
__device__ __forceinline__ void ldsm_x4(uint32_t* r, uint32_t addr) {
    asm volatile("ldmatrix.sync.aligned.m8n8.x4.shared.b16 {%0,%1,%2,%3}, [%4];"
                 : "=r"(r[0]), "=r"(r[1]), "=r"(r[2]), "=r"(r[3]) : "r"(addr));
}
__device__ __forceinline__ void ldsm_x4_t(uint32_t* r, uint32_t addr) {
    asm volatile("ldmatrix.sync.aligned.m8n8.x4.trans.shared.b16 {%0,%1,%2,%3}, [%4];"
                 : "=r"(r[0]), "=r"(r[1]), "=r"(r[2]), "=r"(r[3]) : "r"(addr));
}
__device__ __forceinline__ void mma_bf16(float* d, const uint32_t* a, const uint32_t* b) {
    asm volatile(
        "mma.sync.aligned.m16n8k16.row.col.f32.bf16.bf16.f32 "
        "{%0,%1,%2,%3}, {%4,%5,%6,%7}, {%8,%9}, {%0,%1,%2,%3};"
        : "+f"(d[0]), "+f"(d[1]), "+f"(d[2]), "+f"(d[3])
        : "r"(a[0]), "r"(a[1]), "r"(a[2]), "r"(a[3]), "r"(b[0]), "r"(b[1]));
}
__device__ __forceinline__ uint32_t pack_bf(__nv_bfloat16 x, __nv_bfloat16 y) {
    return ((uint32_t)__bfloat16_as_ushort(y) << 16) | (uint32_t)__bfloat16_as_ushort(x);
}

// ---------------------------------------------------------------------------
// Fused prescan + A conversion. One block per 64x64 tile: load tile into
// registers, reduce max-abs, then convert (masked) to bf16 hi/lo.
// ---------------------------------------------------------------------------
__global__ void conv_a_fused(const float* __restrict__ A,
                             __nv_bfloat16* __restrict__ Ah,
                             __nv_bfloat16* __restrict__ Al) {
    const int kt = blockIdx.x, mt = blockIdx.y, b = blockIdx.z;
    const int tid = threadIdx.x;
    const int row = mt * 64 + (tid >> 2);
    const int colbase = kt * 64 + (tid & 3) * 16;
    const size_t g0 = ((size_t)b * MDIM + row) * KDIM + colbase;

    float4 v[4];
    float mx = 0.0f;
#pragma unroll
    for (int j = 0; j < 4; j++) {
        v[j] = *(const float4*)(A + g0 + j * 4);
        mx = fmaxf(mx, fmaxf(fmaxf(fabsf(v[j].x), fabsf(v[j].y)),
                             fmaxf(fabsf(v[j].z), fabsf(v[j].w))));
    }
#pragma unroll
    for (int o = 16; o; o >>= 1) mx = fmaxf(mx, __shfl_xor_sync(0xffffffffu, mx, o));

    __shared__ float wmax[8];
    __shared__ float s_scale;
    if ((tid & 31) == 0) wmax[tid >> 5] = mx;
    __syncthreads();
    if (tid == 0) {
        float m = wmax[0];
#pragma unroll
        for (int i = 1; i < 8; i++) m = fmaxf(m, wmax[i]);
        s_scale = (m > 1e-6f) ? 1.0f : 0.0f;
    }
    __syncthreads();
    const float s = s_scale;

#pragma unroll
    for (int j = 0; j < 4; j++) {
        float x0 = v[j].x * s, x1 = v[j].y * s, x2 = v[j].z * s, x3 = v[j].w * s;
        __nv_bfloat16 h0 = __float2bfloat16_rn(x0);
        __nv_bfloat16 h1 = __float2bfloat16_rn(x1);
        __nv_bfloat16 h2 = __float2bfloat16_rn(x2);
        __nv_bfloat16 h3 = __float2bfloat16_rn(x3);
        __nv_bfloat16 l0 = __float2bfloat16_rn(x0 - __bfloat162float(h0));
        __nv_bfloat16 l1 = __float2bfloat16_rn(x1 - __bfloat162float(h1));
        __nv_bfloat16 l2 = __float2bfloat16_rn(x2 - __bfloat162float(h2));
        __nv_bfloat16 l3 = __float2bfloat16_rn(x3 - __bfloat162float(h3));
        *(uint2*)(Ah + g0 + j * 4) = make_uint2(pack_bf(h0, h1), pack_bf(h2, h3));
        *(uint2*)(Al + g0 + j * 4) = make_uint2(pack_bf(l0, l1), pack_bf(l2, l3));
    }
}

// ---------------------------------------------------------------------------
// B conversion fp32 -> bf16 hi/lo (no mask).
// ---------------------------------------------------------------------------
__global__ void conv_b(const float* __restrict__ X,
                       __nv_bfloat16* __restrict__ Xh,
                       __nv_bfloat16* __restrict__ Xl) {
    const size_t i4 = (size_t)blockIdx.x * blockDim.x + threadIdx.x;
    float4 v = ((const float4*)X)[i4];
    __nv_bfloat16 h0 = __float2bfloat16_rn(v.x);
    __nv_bfloat16 h1 = __float2bfloat16_rn(v.y);
    __nv_bfloat16 h2 = __float2bfloat16_rn(v.z);
    __nv_bfloat16 h3 = __float2bfloat16_rn(v.w);
    __nv_bfloat16 l0 = __float2bfloat16_rn(v.x - __bfloat162float(h0));
    __nv_bfloat16 l1 = __float2bfloat16_rn(v.y - __bfloat162float(h1));
    __nv_bfloat16 l2 = __float2bfloat16_rn(v.z - __bfloat162float(h2));
    __nv_bfloat16 l3 = __float2bfloat16_rn(v.w - __bfloat162float(h3));
    ((uint2*)Xh)[i4] = make_uint2(pack_bf(h0, h1), pack_bf(h2, h3));
    ((uint2*)Xl)[i4] = make_uint2(pack_bf(l0, l1), pack_bf(l2, l3));
}

// ---------------------------------------------------------------------------
// GEMM: bf16 mma.sync, 3 products, BK=64, 2-stage cp.async pipeline.
// 512 threads = 16 warps as 4(M) x 4(N); warp tile 64x32.
// ---------------------------------------------------------------------------
__global__ __launch_bounds__(512, 1) void gemm_mma(float* __restrict__ C) {
    extern __shared__ char smem[];
    const uint32_t sb = smem_u32(smem);
    const int tid = threadIdx.x;
    const int wid = tid >> 5, lane = tid & 31;
    const int b = blockIdx.z;
    const int bm = blockIdx.y * BM, bn = blockIdx.x * BN;

    const size_t boffA = (size_t)b * MDIM * KDIM;
    const size_t boffB = (size_t)b * KDIM * NDIM;
    const __nv_bfloat16* pAh = g_Ah + boffA;
    const __nv_bfloat16* pAl = g_Al + boffA;
    const __nv_bfloat16* pBh = g_Bh + boffB;
    const __nv_bfloat16* pBl = g_Bl + boffB;

    // A: 256 rows x 8 chunks(16B); swizzle c ^= (r & 7). 2048 chunks/split, 4/thread.
    // B: 64 rows x 16 chunks;      swizzle c ^= (k & 7). 1024 chunks/split, 2/thread.
    auto load_stage = [&](int t) {
        const uint32_t st = sb + (uint32_t)(t & 1) * STAGE_BYTES;
        const int koff = t * BK;
#pragma unroll
        for (int i = 0; i < 4; i++) {
            const int idx = i * 512 + tid;
            const int r = idx >> 3, c = idx & 7;
            const uint32_t so = (uint32_t)(r * 128 + ((c ^ (r & 7)) << 4));
            const size_t g = (size_t)(bm + r) * KDIM + koff + c * 8;
            cpa16(st + so, pAh + g);
            cpa16(st + A_SPLIT_BYTES + so, pAl + g);
        }
        const uint32_t sB = st + 2 * A_SPLIT_BYTES;
#pragma unroll
        for (int i = 0; i < 2; i++) {
            const int idx = i * 512 + tid;
            const int k = idx >> 4, c = idx & 15;
            const uint32_t so = (uint32_t)(k * 256 + ((c ^ (k & 7)) << 4));
            const size_t g = (size_t)(koff + k) * NDIM + bn + c * 8;
            cpa16(sB + so, pBh + g);
            cpa16(sB + B_SPLIT_BYTES + so, pBl + g);
        }
    };

    // warp tiling: 4(M) x 4(N)
    const int wm = (wid >> 2) * 64;
    const int wn = (wid & 3) * 32;

    // ldmatrix lane geometry
    const int a_r = wm + (lane & 15);            // + i*16
    const int a_cL = (lane >> 4);                // + ks*2
    const int b_k = (lane & 15);                 // + ks*16
    const int b_cL = (wn >> 3) + (lane >> 4);    // + j2*2

    float acc[4][4][4];
#pragma unroll
    for (int i = 0; i < 4; i++)
#pragma unroll
        for (int j = 0; j < 4; j++)
#pragma unroll
            for (int q = 0; q < 4; q++) acc[i][j][q] = 0.0f;

    // prologue: stage 0
    load_stage(0);
    asm volatile("cp.async.commit_group;" ::: "memory");

    for (int t = 0; t < NK; ++t) {
        asm volatile("cp.async.wait_group 0;" ::: "memory");
        __syncthreads();

        if (t + 1 < NK) {
            load_stage(t + 1);
            asm volatile("cp.async.commit_group;" ::: "memory");
        }

        const uint32_t st = sb + (uint32_t)(t & 1) * STAGE_BYTES;
        const uint32_t sAh = st;
        const uint32_t sAl = st + A_SPLIT_BYTES;
        const uint32_t sBh = st + 2 * A_SPLIT_BYTES;
        const uint32_t sBl = sBh + B_SPLIT_BYTES;

#pragma unroll
        for (int ks = 0; ks < 4; ks++) {
            uint32_t ah[4][4], al[4][4], bh[2][4], bl[2][4];
#pragma unroll
            for (int i = 0; i < 4; i++) {
                const int r = a_r + i * 16;
                const int c = ks * 2 + a_cL;
                const uint32_t off = (uint32_t)(r * 128 + ((c ^ (r & 7)) << 4));
                ldsm_x4(ah[i], sAh + off);
                ldsm_x4(al[i], sAl + off);
            }
#pragma unroll
            for (int j2 = 0; j2 < 2; j2++) {
                const int k = ks * 16 + b_k;
                const int c = b_cL + j2 * 2;
                const uint32_t off = (uint32_t)(k * 256 + ((c ^ (k & 7)) << 4));
                ldsm_x4_t(bh[j2], sBh + off);
                ldsm_x4_t(bl[j2], sBl + off);
            }
#pragma unroll
            for (int i = 0; i < 4; i++)
#pragma unroll
                for (int j2 = 0; j2 < 2; j2++)
#pragma unroll
                    for (int n8 = 0; n8 < 2; n8++) {
                        float* a4 = acc[i][j2 * 2 + n8];
                        mma_bf16(a4, ah[i], &bh[j2][n8 * 2]);
                        mma_bf16(a4, ah[i], &bl[j2][n8 * 2]);
                        mma_bf16(a4, al[i], &bh[j2][n8 * 2]);
                    }
        }
        // stage (t+1)&1 is only overwritten after next iteration's barrier.
    }

    // epilogue
    float* Cb = C + (size_t)b * MDIM * NDIM;
    const int r0 = bm + wm + (lane >> 2);
    const int c0 = bn + wn + (lane & 3) * 2;
#pragma unroll
    for (int i = 0; i < 4; i++) {
#pragma unroll
        for (int j = 0; j < 4; j++) {
            const int row = r0 + i * 16;
            const int col = c0 + j * 8;
            *(float2*)&Cb[(size_t)row * NDIM + col] = make_float2(acc[i][j][0], acc[i][j][1]);
            *(float2*)&Cb[(size_t)(row + 8) * NDIM + col] = make_float2(acc[i][j][2], acc[i][j][3]);
        }
    }
}

extern "C" void kernel_launch(void* const* d_in, const int* in_sizes, int n_in,
                              void* d_out, int out_size) {
    const float* a = (const float*)d_in[0];
    const float* b = (const float*)d_in[1];
    float* out = (float*)d_out;

    __nv_bfloat16 *Ah, *Al, *Bh, *Bl;
    cudaGetSymbolAddress((void**)&Ah, g_Ah);
    cudaGetSymbolAddress((void**)&Al, g_Al);
    cudaGetSymbolAddress((void**)&Bh, g_Bh);
    cudaGetSymbolAddress((void**)&Bl, g_Bl);

    dim3 agrid(32, 32, BATCH);
    conv_a_fused<<<agrid, 256>>>(a, Ah, Al);

    const int conv_blocks = (BATCH * KDIM * NDIM / 4) / 256;   // 32768
    conv_b<<<conv_blocks, 256>>>(b, Bh, Bl);

    cudaFuncSetAttribute(gemm_mma, cudaFuncAttributeMaxDynamicSharedMemorySize, SMEM_TOTAL);
    dim3 grid(NDIM / BN, MDIM / BM, BATCH);
    gemm_mma<<<grid, 512, SMEM_TOTAL>>>(out);
}

// round 7
// speedup vs baseline: 1.5117x; 1.5117x over previous
#include <cuda_runtime.h>
#include <cuda_bf16.h>
#include <cstdint>

// SparseBMM: y[b,m,n] = sum_k A_masked[b,m,k] * B[b,k,n], fp32 [8,2048,2048].
// A_masked zeroes 64x64 tiles of A whose max-abs <= 1e-6.
// bf16 mma.sync m16n8k16, hi/lo split (3 products), fp32 accumulate.
// R7: R5 GEMM (BK=32, 4-stage) + product-major MMA interleave;
//     single fused conversion kernel (prescan re-reads via L1, no spills).

#define BATCH 8
#define MDIM 2048
#define NDIM 2048
#define KDIM 2048

#define BM 256
#define BN 128
#define BK 32
#define STAGES 4
#define NK (KDIM / BK)          // 64

#define A_ST_BYTES 16384        // 256 rows x 32 bf16 = 256x64B
#define B_ST_BYTES 8192         // 32 rows x 128 bf16 = 32x256B
#define STAGE_BYTES (2 * A_ST_BYTES + 2 * B_ST_BYTES)   // 49152
#define SMEM_TOTAL (STAGES * STAGE_BYTES)               // 196608

#define A_TILE_BLOCKS (BATCH * 32 * 32)                 // 8192
#define B_CONV_BLOCKS ((BATCH * KDIM * NDIM / 4) / 256) // 32768

__device__ __nv_bfloat16 g_Ah[(size_t)BATCH * MDIM * KDIM];
__device__ __nv_bfloat16 g_Al[(size_t)BATCH * MDIM * KDIM];
__device__ __nv_bfloat16 g_Bh[(size_t)BATCH * KDIM * NDIM];
__device__ __nv_bfloat16 g_Bl[(size_t)BATCH * KDIM * NDIM];

// ---------------- helpers ----------------
__device__ __forceinline__ uint32_t smem_u32(const void* p) {
    uint32_t a;
    asm("{ .reg .u64 t; cvta.to.shared.u64 t, %1; cvt.u32.u64 %0, t; }" : "=r"(a) : "l"(p));
    return a;
}
__device__ __forceinline__ void cpa16(uint32_t dst, const void* src) {
    asm volatile("cp.async.cg.shared.global [%0], [%1], 16;" :: "r"(dst), "l"(src));
}
__device__ __forceinline__ void ldsm_x4(uint32_t* r, uint32_t addr) {
    asm volatile("ldmatrix.sync.aligned.m8n8.x4.shared.b16 {%0,%1,%2,%3}, [%4];"
                 : "=r"(r[0]), "=r"(r[1]), "=r"(r[2]), "=r"(r[3]) : "r"(addr));
}
__device__ __forceinline__ void ldsm_x4_t(uint32_t* r, uint32_t addr) {
    asm volatile("ldmatrix.sync.aligned.m8n8.x4.trans.shared.b16 {%0,%1,%2,%3}, [%4];"
                 : "=r"(r[0]), "=r"(r[1]), "=r"(r[2]), "=r"(r[3]) : "r"(addr));
}
__device__ __forceinline__ void mma_bf16(float* d, const uint32_t* a, const uint32_t* b) {
    asm volatile(
        "mma.sync.aligned.m16n8k16.row.col.f32.bf16.bf16.f32 "
        "{%0,%1,%2,%3}, {%4,%5,%6,%7}, {%8,%9}, {%0,%1,%2,%3};"
        : "+f"(d[0]), "+f"(d[1]), "+f"(d[2]), "+f"(d[3])
        : "r"(a[0]), "r"(a[1]), "r"(a[2]), "r"(a[3]), "r"(b[0]), "r"(b[1]));
}
__device__ __forceinline__ uint32_t pack_bf(__nv_bfloat16 x, __nv_bfloat16 y) {
    return ((uint32_t)__bfloat16_as_ushort(y) << 16) | (uint32_t)__bfloat16_as_ushort(x);
}
__device__ __forceinline__ uint2 split4(float x0, float x1, float x2, float x3,
                                        uint2* lo) {
    __nv_bfloat16 h0 = __float2bfloat16_rn(x0);
    __nv_bfloat16 h1 = __float2bfloat16_rn(x1);
    __nv_bfloat16 h2 = __float2bfloat16_rn(x2);
    __nv_bfloat16 h3 = __float2bfloat16_rn(x3);
    __nv_bfloat16 l0 = __float2bfloat16_rn(x0 - __bfloat162float(h0));
    __nv_bfloat16 l1 = __float2bfloat16_rn(x1 - __bfloat162float(h1));
    __nv_bfloat16 l2 = __float2bfloat16_rn(x2 - __bfloat162float(h2));
    __nv_bfloat16 l3 = __float2bfloat16_rn(x3 - __bfloat162float(h3));
    *lo = make_uint2(pack_bf(l0, l1), pack_bf(l2, l3));
    return make_uint2(pack_bf(h0, h1), pack_bf(h2, h3));
}

// ---------------------------------------------------------------------------
// Fused conversion: blocks [0, A_TILE_BLOCKS) handle A 64x64 tiles (prescan
// pass + convert pass; second pass re-reads gmem through L1 so nothing fp32
// stays live across the barrier). Remaining blocks stream-convert B.
// ---------------------------------------------------------------------------
__global__ __launch_bounds__(256) void conv_all(const float* __restrict__ A,
                                                const float* __restrict__ B,
                                                __nv_bfloat16* __restrict__ Ah,
                                                __nv_bfloat16* __restrict__ Al,
                                                __nv_bfloat16* __restrict__ Bh,
                                                __nv_bfloat16* __restrict__ Bl) {
    const int tid = threadIdx.x;
    if (blockIdx.x < A_TILE_BLOCKS) {
        const int tile = blockIdx.x;
        const int kt = tile & 31, mt = (tile >> 5) & 31, b = tile >> 10;
        // 1024 float4 per tile; 4 per thread; q = i*256+tid -> row=q>>4, c4=q&15
        // warp covers 2 full rows (256B each) -> fully coalesced sectors.
        const size_t tbase = ((size_t)b * MDIM + (size_t)mt * 64) * KDIM + (size_t)kt * 64;

        float mx = 0.0f;
#pragma unroll
        for (int i = 0; i < 4; i++) {
            const int q = i * 256 + tid;
            const int row = q >> 4, c4 = q & 15;
            const float4 v = *(const float4*)(A + tbase + (size_t)row * KDIM + c4 * 4);
            mx = fmaxf(mx, fmaxf(fmaxf(fabsf(v.x), fabsf(v.y)),
                                 fmaxf(fabsf(v.z), fabsf(v.w))));
        }
#pragma unroll
        for (int o = 16; o; o >>= 1) mx = fmaxf(mx, __shfl_xor_sync(0xffffffffu, mx, o));

        __shared__ float wmax[8];
        __shared__ float s_scale;
        if ((tid & 31) == 0) wmax[tid >> 5] = mx;
        __syncthreads();
        if (tid == 0) {
            float m = wmax[0];
#pragma unroll
            for (int i = 1; i < 8; i++) m = fmaxf(m, wmax[i]);
            s_scale = (m > 1e-6f) ? 1.0f : 0.0f;
        }
        __syncthreads();
        const float s = s_scale;

#pragma unroll
        for (int i = 0; i < 4; i++) {
            const int q = i * 256 + tid;
            const int row = q >> 4, c4 = q & 15;
            const size_t g = tbase + (size_t)row * KDIM + c4 * 4;
            const float4 v = *(const float4*)(A + g);   // L1 hit
            uint2 lo, hi;
            hi = split4(v.x * s, v.y * s, v.z * s, v.w * s, &lo);
            *(uint2*)(Ah + g) = hi;
            *(uint2*)(Al + g) = lo;
        }
    } else {
        const size_t i4 = (size_t)(blockIdx.x - A_TILE_BLOCKS) * 256 + tid;
        const float4 v = ((const float4*)B)[i4];
        uint2 lo, hi;
        hi = split4(v.x, v.y, v.z, v.w, &lo);
        ((uint2*)Bh)[i4] = hi;
        ((uint2*)Bl)[i4] = lo;
    }
}

// ---------------------------------------------------------------------------
// GEMM: bf16 mma.sync, 3 products (product-major interleave), 4-stage
// cp.async pipeline. 512 threads = 16 warps as 4(M) x 4(N); warp tile 64x32.
// ---------------------------------------------------------------------------
__global__ __launch_bounds__(512, 1) void gemm_mma(float* __restrict__ C) {
    extern __shared__ char smem[];
    const uint32_t sb = smem_u32(smem);
    const int tid = threadIdx.x;
    const int wid = tid >> 5, lane = tid & 31;
    const int b = blockIdx.z;
    const int bm = blockIdx.y * BM, bn = blockIdx.x * BN;

    const size_t boffA = (size_t)b * MDIM * KDIM;
    const size_t boffB = (size_t)b * KDIM * NDIM;
    const __nv_bfloat16* pAh = g_Ah + boffA;
    const __nv_bfloat16* pAl = g_Al + boffA;
    const __nv_bfloat16* pBh = g_Bh + boffB;
    const __nv_bfloat16* pBl = g_Bl + boffB;

    // cp.async geometry (512 threads)
    const int ar = tid >> 2, ac = tid & 3;       // A: rows ar, ar+128; chunk ac
    const int bk = tid >> 4, bc = tid & 15;      // B: row bk; chunk bc
    const uint32_t saw = (uint32_t)(ar * 4 + (ac ^ ((ar >> 1) & 3))) * 16;
    const uint32_t sbw = (uint32_t)(bk * 16 + (bc ^ (bk & 7))) * 16;

    const __nv_bfloat16* gAh0 = pAh + (size_t)(bm + ar) * KDIM + ac * 8;
    const __nv_bfloat16* gAl0 = pAl + (size_t)(bm + ar) * KDIM + ac * 8;
    const __nv_bfloat16* gBh0 = pBh + (size_t)bk * NDIM + bn + bc * 8;
    const __nv_bfloat16* gBl0 = pBl + (size_t)bk * NDIM + bn + bc * 8;

    auto load_stage = [&](int t) {
        const uint32_t st = sb + (uint32_t)(t % STAGES) * STAGE_BYTES;
        const size_t aoff = (size_t)(t * BK);
        const size_t boff = (size_t)(t * BK) * NDIM;
        cpa16(st + saw,                     gAh0 + aoff);
        cpa16(st + saw + 8192,              gAh0 + aoff + (size_t)128 * KDIM);
        cpa16(st + A_ST_BYTES + saw,        gAl0 + aoff);
        cpa16(st + A_ST_BYTES + saw + 8192, gAl0 + aoff + (size_t)128 * KDIM);
        const uint32_t sB = st + 2 * A_ST_BYTES;
        cpa16(sB + sbw,                     gBh0 + boff);
        cpa16(sB + B_ST_BYTES + sbw,        gBl0 + boff);
    };

    // warp tiling: 4(M) x 4(N)
    const int wm = (wid >> 2) * 64;
    const int wn = (wid & 3) * 32;

    // ldmatrix lane geometry
    const int a_r = wm + (lane & 15);            // + i*16
    const int a_cL = (lane >> 4);                // + ks*2
    const int b_k = (lane & 15);                 // + ks*16
    const int b_cL = (wn >> 3) + (lane >> 4);    // + j2*2

    float acc[4][4][4];
#pragma unroll
    for (int i = 0; i < 4; i++)
#pragma unroll
        for (int j = 0; j < 4; j++)
#pragma unroll
            for (int q = 0; q < 4; q++) acc[i][j][q] = 0.0f;

    // prologue
#pragma unroll
    for (int t = 0; t < STAGES - 1; ++t) {
        load_stage(t);
        asm volatile("cp.async.commit_group;" ::: "memory");
    }

    for (int t = 0; t < NK; ++t) {
        asm volatile("cp.async.wait_group %0;" :: "n"(STAGES - 2) : "memory");
        __syncthreads();

        if (t + STAGES - 1 < NK) load_stage(t + STAGES - 1);
        asm volatile("cp.async.commit_group;" ::: "memory");

        const uint32_t st = sb + (uint32_t)(t % STAGES) * STAGE_BYTES;
        const uint32_t sAh = st;
        const uint32_t sAl = st + A_ST_BYTES;
        const uint32_t sBh = st + 2 * A_ST_BYTES;
        const uint32_t sBl = sBh + B_ST_BYTES;

#pragma unroll
        for (int ks = 0; ks < 2; ks++) {
            uint32_t ah[4][4], al[4][4], bh[2][4], bl[2][4];
#pragma unroll
            for (int i = 0; i < 4; i++) {
                const int r = a_r + i * 16;
                const int c = ks * 2 + a_cL;
                const uint32_t off = (uint32_t)(r * 4 + (c ^ ((r >> 1) & 3))) * 16;
                ldsm_x4(ah[i], sAh + off);
                ldsm_x4(al[i], sAl + off);
            }
#pragma unroll
            for (int j2 = 0; j2 < 2; j2++) {
                const int k = ks * 16 + b_k;
                const int c = b_cL + j2 * 2;
                const uint32_t off = (uint32_t)(k * 16 + (c ^ (k & 7))) * 16;
                ldsm_x4_t(bh[j2], sBh + off);
                ldsm_x4_t(bl[j2], sBl + off);
            }
            // product-major: dependent reuse of each accumulator is 16 MMAs apart
#pragma unroll
            for (int i = 0; i < 4; i++)
#pragma unroll
                for (int j2 = 0; j2 < 2; j2++)
#pragma unroll
                    for (int n8 = 0; n8 < 2; n8++)
                        mma_bf16(acc[i][j2 * 2 + n8], ah[i], &bh[j2][n8 * 2]);
#pragma unroll
            for (int i = 0; i < 4; i++)
#pragma unroll
                for (int j2 = 0; j2 < 2; j2++)
#pragma unroll
                    for (int n8 = 0; n8 < 2; n8++)
                        mma_bf16(acc[i][j2 * 2 + n8], ah[i], &bl[j2][n8 * 2]);
#pragma unroll
            for (int i = 0; i < 4; i++)
#pragma unroll
                for (int j2 = 0; j2 < 2; j2++)
#pragma unroll
                    for (int n8 = 0; n8 < 2; n8++)
                        mma_bf16(acc[i][j2 * 2 + n8], al[i], &bh[j2][n8 * 2]);
        }
        // stage reuse protected by next iteration's top-of-loop barrier
    }

    // epilogue
    float* Cb = C + (size_t)b * MDIM * NDIM;
    const int r0 = bm + wm + (lane >> 2);
    const int c0 = bn + wn + (lane & 3) * 2;
#pragma unroll
    for (int i = 0; i < 4; i++) {
#pragma unroll
        for (int j = 0; j < 4; j++) {
            const int row = r0 + i * 16;
            const int col = c0 + j * 8;
            *(float2*)&Cb[(size_t)row * NDIM + col] = make_float2(acc[i][j][0], acc[i][j][1]);
            *(float2*)&Cb[(size_t)(row + 8) * NDIM + col] = make_float2(acc[i][j][2], acc[i][j][3]);
        }
    }
}

extern "C" void kernel_launch(void* const* d_in, const int* in_sizes, int n_in,
                              void* d_out, int out_size) {
    const float* a = (const float*)d_in[0];
    const float* b = (const float*)d_in[1];
    float* out = (float*)d_out;

    __nv_bfloat16 *Ah, *Al, *Bh, *Bl;
    cudaGetSymbolAddress((void**)&Ah, g_Ah);
    cudaGetSymbolAddress((void**)&Al, g_Al);
    cudaGetSymbolAddress((void**)&Bh, g_Bh);
    cudaGetSymbolAddress((void**)&Bl, g_Bl);

    conv_all<<<A_TILE_BLOCKS + B_CONV_BLOCKS, 256>>>(a, b, Ah, Al, Bh, Bl);

    cudaFuncSetAttribute(gemm_mma, cudaFuncAttributeMaxDynamicSharedMemorySize, SMEM_TOTAL);
    dim3 grid(NDIM / BN, MDIM / BM, BATCH);
    gemm_mma<<<grid, 512, SMEM_TOTAL>>>(out);
}

// round 9
// speedup vs baseline: 1.5125x; 1.0005x over previous
#include <cuda_runtime.h>
#include <cuda_bf16.h>
#include <cstdint>

// SparseBMM: y[b,m,n] = sum_k A_masked[b,m,k] * B[b,k,n], fp32 [8,2048,2048].
// A_masked zeroes 64x64 tiles of A whose max-abs <= 1e-6.
// bf16 mma.sync m16n8k16, hi/lo split (3 products), fp32 accumulate.
// R8: 256-thread CTAs, BM=BN=128, 3 stages (96KB smem) -> 2 CTAs/SM:
//     two independent barrier domains per SM hide bar/wait stalls.

#define BATCH 8
#define MDIM 2048
#define NDIM 2048
#define KDIM 2048

#define BM 128
#define BN 128
#define BK 32
#define STAGES 3
#define NK (KDIM / BK)          // 64

#define A_ST_BYTES 8192         // 128 rows x 32 bf16
#define B_ST_BYTES 8192         // 32 rows x 128 bf16
#define STAGE_BYTES (2 * A_ST_BYTES + 2 * B_ST_BYTES)   // 32768
#define SMEM_TOTAL (STAGES * STAGE_BYTES)               // 98304

#define A_TILE_BLOCKS (BATCH * 32 * 32)                 // 8192
#define B_CONV_BLOCKS ((BATCH * KDIM * NDIM / 4) / 256) // 32768

__device__ __nv_bfloat16 g_Ah[(size_t)BATCH * MDIM * KDIM];
__device__ __nv_bfloat16 g_Al[(size_t)BATCH * MDIM * KDIM];
__device__ __nv_bfloat16 g_Bh[(size_t)BATCH * KDIM * NDIM];
__device__ __nv_bfloat16 g_Bl[(size_t)BATCH * KDIM * NDIM];

// ---------------- helpers ----------------
__device__ __forceinline__ uint32_t smem_u32(const void* p) {
    uint32_t a;
    asm("{ .reg .u64 t; cvta.to.shared.u64 t, %1; cvt.u32.u64 %0, t; }" : "=r"(a) : "l"(p));
    return a;
}
__device__ __forceinline__ void cpa16(uint32_t dst, const void* src) {
    asm volatile("cp.async.cg.shared.global [%0], [%1], 16;" :: "r"(dst), "l"(src));
}
__device__ __forceinline__ void ldsm_x4(uint32_t* r, uint32_t addr) {
    asm volatile("ldmatrix.sync.aligned.m8n8.x4.shared.b16 {%0,%1,%2,%3}, [%4];"
                 : "=r"(r[0]), "=r"(r[1]), "=r"(r[2]), "=r"(r[3]) : "r"(addr));
}
__device__ __forceinline__ void ldsm_x4_t(uint32_t* r, uint32_t addr) {
    asm volatile("ldmatrix.sync.aligned.m8n8.x4.trans.shared.b16 {%0,%1,%2,%3}, [%4];"
                 : "=r"(r[0]), "=r"(r[1]), "=r"(r[2]), "=r"(r[3]) : "r"(addr));
}
__device__ __forceinline__ void mma_bf16(float* d, const uint32_t* a, const uint32_t* b) {
    asm volatile(
        "mma.sync.aligned.m16n8k16.row.col.f32.bf16.bf16.f32 "
        "{%0,%1,%2,%3}, {%4,%5,%6,%7}, {%8,%9}, {%0,%1,%2,%3};"
        : "+f"(d[0]), "+f"(d[1]), "+f"(d[2]), "+f"(d[3])
        : "r"(a[0]), "r"(a[1]), "r"(a[2]), "r"(a[3]), "r"(b[0]), "r"(b[1]));
}
__device__ __forceinline__ uint32_t pack_bf(__nv_bfloat16 x, __nv_bfloat16 y) {
    return ((uint32_t)__bfloat16_as_ushort(y) << 16) | (uint32_t)__bfloat16_as_ushort(x);
}
__device__ __forceinline__ uint2 split4(float x0, float x1, float x2, float x3,
                                        uint2* lo) {
    __nv_bfloat16 h0 = __float2bfloat16_rn(x0);
    __nv_bfloat16 h1 = __float2bfloat16_rn(x1);
    __nv_bfloat16 h2 = __float2bfloat16_rn(x2);
    __nv_bfloat16 h3 = __float2bfloat16_rn(x3);
    __nv_bfloat16 l0 = __float2bfloat16_rn(x0 - __bfloat162float(h0));
    __nv_bfloat16 l1 = __float2bfloat16_rn(x1 - __bfloat162float(h1));
    __nv_bfloat16 l2 = __float2bfloat16_rn(x2 - __bfloat162float(h2));
    __nv_bfloat16 l3 = __float2bfloat16_rn(x3 - __bfloat162float(h3));
    *lo = make_uint2(pack_bf(l0, l1), pack_bf(l2, l3));
    return make_uint2(pack_bf(h0, h1), pack_bf(h2, h3));
}

// ---------------------------------------------------------------------------
// Fused conversion (unchanged from R7): A-tile blocks do prescan + masked
// convert (second pass re-reads via L1); remaining blocks stream-convert B.
// ---------------------------------------------------------------------------
__global__ __launch_bounds__(256) void conv_all(const float* __restrict__ A,
                                                const float* __restrict__ B,
                                                __nv_bfloat16* __restrict__ Ah,
                                                __nv_bfloat16* __restrict__ Al,
                                                __nv_bfloat16* __restrict__ Bh,
                                                __nv_bfloat16* __restrict__ Bl) {
    const int tid = threadIdx.x;
    if (blockIdx.x < A_TILE_BLOCKS) {
        const int tile = blockIdx.x;
        const int kt = tile & 31, mt = (tile >> 5) & 31, b = tile >> 10;
        const size_t tbase = ((size_t)b * MDIM + (size_t)mt * 64) * KDIM + (size_t)kt * 64;

        float mx = 0.0f;
#pragma unroll
        for (int i = 0; i < 4; i++) {
            const int q = i * 256 + tid;
            const int row = q >> 4, c4 = q & 15;
            const float4 v = *(const float4*)(A + tbase + (size_t)row * KDIM + c4 * 4);
            mx = fmaxf(mx, fmaxf(fmaxf(fabsf(v.x), fabsf(v.y)),
                                 fmaxf(fabsf(v.z), fabsf(v.w))));
        }
#pragma unroll
        for (int o = 16; o; o >>= 1) mx = fmaxf(mx, __shfl_xor_sync(0xffffffffu, mx, o));

        __shared__ float wmax[8];
        __shared__ float s_scale;
        if ((tid & 31) == 0) wmax[tid >> 5] = mx;
        __syncthreads();
        if (tid == 0) {
            float m = wmax[0];
#pragma unroll
            for (int i = 1; i < 8; i++) m = fmaxf(m, wmax[i]);
            s_scale = (m > 1e-6f) ? 1.0f : 0.0f;
        }
        __syncthreads();
        const float s = s_scale;

#pragma unroll
        for (int i = 0; i < 4; i++) {
            const int q = i * 256 + tid;
            const int row = q >> 4, c4 = q & 15;
            const size_t g = tbase + (size_t)row * KDIM + c4 * 4;
            const float4 v = *(const float4*)(A + g);   // L1 hit
            uint2 lo, hi;
            hi = split4(v.x * s, v.y * s, v.z * s, v.w * s, &lo);
            *(uint2*)(Ah + g) = hi;
            *(uint2*)(Al + g) = lo;
        }
    } else {
        const size_t i4 = (size_t)(blockIdx.x - A_TILE_BLOCKS) * 256 + tid;
        const float4 v = ((const float4*)B)[i4];
        uint2 lo, hi;
        hi = split4(v.x, v.y, v.z, v.w, &lo);
        ((uint2*)Bh)[i4] = hi;
        ((uint2*)Bl)[i4] = lo;
    }
}

// ---------------------------------------------------------------------------
// GEMM: bf16 mma.sync, 3 products, 3-stage cp.async pipeline.
// 256 threads = 8 warps as 2(M) x 4(N); warp tile 64x32. 2 CTAs/SM.
// ---------------------------------------------------------------------------
__global__ __launch_bounds__(256, 2) void gemm_mma(float* __restrict__ C) {
    extern __shared__ char smem[];
    const uint32_t sb = smem_u32(smem);
    const int tid = threadIdx.x;
    const int wid = tid >> 5, lane = tid & 31;
    const int b = blockIdx.z;
    const int bm = blockIdx.y * BM, bn = blockIdx.x * BN;

    const size_t boffA = (size_t)b * MDIM * KDIM;
    const size_t boffB = (size_t)b * KDIM * NDIM;
    const __nv_bfloat16* pAh = g_Ah + boffA;
    const __nv_bfloat16* pAl = g_Al + boffA;
    const __nv_bfloat16* pBh = g_Bh + boffB;
    const __nv_bfloat16* pBl = g_Bl + boffB;

    // cp.async geometry (256 threads)
    const int ar = tid >> 2, ac = tid & 3;       // A: rows ar, ar+64; chunk ac
    const int bk = tid >> 3, bc = tid & 7;       // B: row bk; chunks bc, bc+8
    const uint32_t saw = (uint32_t)(ar * 4 + (ac ^ ((ar >> 1) & 3))) * 16;  // +4096 for row+64
    const uint32_t sbw = (uint32_t)(bk * 16 + (bc ^ (bk & 7))) * 16;        // +128 for chunk+8

    const __nv_bfloat16* gAh0 = pAh + (size_t)(bm + ar) * KDIM + ac * 8;
    const __nv_bfloat16* gAl0 = pAl + (size_t)(bm + ar) * KDIM + ac * 8;
    const __nv_bfloat16* gBh0 = pBh + (size_t)bk * NDIM + bn + bc * 8;
    const __nv_bfloat16* gBl0 = pBl + (size_t)bk * NDIM + bn + bc * 8;

    auto load_stage = [&](int t) {
        const uint32_t st = sb + (uint32_t)(t % STAGES) * STAGE_BYTES;
        const size_t aoff = (size_t)(t * BK);
        const size_t boff = (size_t)(t * BK) * NDIM;
        cpa16(st + saw,                     gAh0 + aoff);
        cpa16(st + saw + 4096,              gAh0 + aoff + (size_t)64 * KDIM);
        cpa16(st + A_ST_BYTES + saw,        gAl0 + aoff);
        cpa16(st + A_ST_BYTES + saw + 4096, gAl0 + aoff + (size_t)64 * KDIM);
        const uint32_t sB = st + 2 * A_ST_BYTES;
        cpa16(sB + sbw,                     gBh0 + boff);
        cpa16(sB + sbw + 128,               gBh0 + boff + 64);
        cpa16(sB + B_ST_BYTES + sbw,        gBl0 + boff);
        cpa16(sB + B_ST_BYTES + sbw + 128,  gBl0 + boff + 64);
    };

    // warp tiling: 2(M) x 4(N)
    const int wm = (wid >> 2) * 64;      // 0 or 64
    const int wn = (wid & 3) * 32;       // 0,32,64,96

    // ldmatrix lane geometry
    const int a_r = wm + (lane & 15);            // + i*16
    const int a_cL = (lane >> 4);                // + ks*2
    const int b_k = (lane & 15);                 // + ks*16
    const int b_cL = (wn >> 3) + (lane >> 4);    // + j2*2

    float acc[4][4][4];
#pragma unroll
    for (int i = 0; i < 4; i++)
#pragma unroll
        for (int j = 0; j < 4; j++)
#pragma unroll
            for (int q = 0; q < 4; q++) acc[i][j][q] = 0.0f;

    // prologue: stages 0..STAGES-2
#pragma unroll
    for (int t = 0; t < STAGES - 1; ++t) {
        load_stage(t);
        asm volatile("cp.async.commit_group;" ::: "memory");
    }

    for (int t = 0; t < NK; ++t) {
        asm volatile("cp.async.wait_group %0;" :: "n"(STAGES - 2) : "memory");
        __syncthreads();

        if (t + STAGES - 1 < NK) load_stage(t + STAGES - 1);
        asm volatile("cp.async.commit_group;" ::: "memory");

        const uint32_t st = sb + (uint32_t)(t % STAGES) * STAGE_BYTES;
        const uint32_t sAh = st;
        const uint32_t sAl = st + A_ST_BYTES;
        const uint32_t sBh = st + 2 * A_ST_BYTES;
        const uint32_t sBl = sBh + B_ST_BYTES;

#pragma unroll
        for (int ks = 0; ks < 2; ks++) {
            uint32_t ah[4][4], al[4][4], bh[2][4], bl[2][4];
#pragma unroll
            for (int i = 0; i < 4; i++) {
                const int r = a_r + i * 16;
                const int c = ks * 2 + a_cL;
                const uint32_t off = (uint32_t)(r * 4 + (c ^ ((r >> 1) & 3))) * 16;
                ldsm_x4(ah[i], sAh + off);
                ldsm_x4(al[i], sAl + off);
            }
#pragma unroll
            for (int j2 = 0; j2 < 2; j2++) {
                const int k = ks * 16 + b_k;
                const int c = b_cL + j2 * 2;
                const uint32_t off = (uint32_t)(k * 16 + (c ^ (k & 7))) * 16;
                ldsm_x4_t(bh[j2], sBh + off);
                ldsm_x4_t(bl[j2], sBl + off);
            }
#pragma unroll
            for (int i = 0; i < 4; i++)
#pragma unroll
                for (int j2 = 0; j2 < 2; j2++)
#pragma unroll
                    for (int n8 = 0; n8 < 2; n8++) {
                        float* a4 = acc[i][j2 * 2 + n8];
                        mma_bf16(a4, ah[i], &bh[j2][n8 * 2]);
                        mma_bf16(a4, ah[i], &bl[j2][n8 * 2]);
                        mma_bf16(a4, al[i], &bh[j2][n8 * 2]);
                    }
        }
        // stage reuse protected by next iteration's top-of-loop barrier
    }

    // epilogue
    float* Cb = C + (size_t)b * MDIM * NDIM;
    const int r0 = bm + wm + (lane >> 2);
    const int c0 = bn + wn + (lane & 3) * 2;
#pragma unroll
    for (int i = 0; i < 4; i++) {
#pragma unroll
        for (int j = 0; j < 4; j++) {
            const int row = r0 + i * 16;
            const int col = c0 + j * 8;
            *(float2*)&Cb[(size_t)row * NDIM + col] = make_float2(acc[i][j][0], acc[i][j][1]);
            *(float2*)&Cb[(size_t)(row + 8) * NDIM + col] = make_float2(acc[i][j][2], acc[i][j][3]);
        }
    }
}

extern "C" void kernel_launch(void* const* d_in, const int* in_sizes, int n_in,
                              void* d_out, int out_size) {
    const float* a = (const float*)d_in[0];
    const float* b = (const float*)d_in[1];
    float* out = (float*)d_out;

    __nv_bfloat16 *Ah, *Al, *Bh, *Bl;
    cudaGetSymbolAddress((void**)&Ah, g_Ah);
    cudaGetSymbolAddress((void**)&Al, g_Al);
    cudaGetSymbolAddress((void**)&Bh, g_Bh);
    cudaGetSymbolAddress((void**)&Bl, g_Bl);

    conv_all<<<A_TILE_BLOCKS + B_CONV_BLOCKS, 256>>>(a, b, Ah, Al, Bh, Bl);

    cudaFuncSetAttribute(gemm_mma, cudaFuncAttributeMaxDynamicSharedMemorySize, SMEM_TOTAL);
    dim3 grid(NDIM / BN, MDIM / BM, BATCH);
    gemm_mma<<<grid, 256, SMEM_TOTAL>>>(out);
}

// round 11
// speedup vs baseline: 3.1540x; 2.0854x over previous
#include <cuda_runtime.h>
#include <cuda_fp16.h>
#include <cstdint>

// SparseBMM: y[b,m,n] = sum_k A_masked[b,m,k] * B[b,k,n], fp32 [8,2048,2048].
// A_masked zeroes 64x64 tiles of A whose max-abs <= 1e-6.
// R11: single-product fp16 mma.sync m16n8k16 (fp32 accumulate), 5-stage pipe.
//      Norm-level rel err ~3e-4 (<1e-3 tol). 3x fewer MMAs than hi/lo split.

#define BATCH 8
#define MDIM 2048
#define NDIM 2048
#define KDIM 2048

#define BM 256
#define BN 128
#define BK 32
#define STAGES 5
#define NK (KDIM / BK)          // 64

#define A_ST_BYTES 16384        // 256 rows x 32 fp16
#define B_ST_BYTES 8192         // 32 rows x 128 fp16
#define STAGE_BYTES (A_ST_BYTES + B_ST_BYTES)   // 24576
#define SMEM_TOTAL (STAGES * STAGE_BYTES)       // 122880

#define A_TILE_BLOCKS (BATCH * 32 * 32)                 // 8192
#define B_CONV_BLOCKS ((BATCH * KDIM * NDIM / 4) / 256) // 32768

__device__ __half g_Ah[(size_t)BATCH * MDIM * KDIM];
__device__ __half g_Bh[(size_t)BATCH * KDIM * NDIM];

// ---------------- helpers ----------------
__device__ __forceinline__ uint32_t smem_u32(const void* p) {
    uint32_t a;
    asm("{ .reg .u64 t; cvta.to.shared.u64 t, %1; cvt.u32.u64 %0, t; }" : "=r"(a) : "l"(p));
    return a;
}
__device__ __forceinline__ void cpa16(uint32_t dst, const void* src) {
    asm volatile("cp.async.cg.shared.global [%0], [%1], 16;" :: "r"(dst), "l"(src));
}
__device__ __forceinline__ void ldsm_x4(uint32_t* r, uint32_t addr) {
    asm volatile("ldmatrix.sync.aligned.m8n8.x4.shared.b16 {%0,%1,%2,%3}, [%4];"
                 : "=r"(r[0]), "=r"(r[1]), "=r"(r[2]), "=r"(r[3]) : "r"(addr));
}
__device__ __forceinline__ void ldsm_x4_t(uint32_t* r, uint32_t addr) {
    asm volatile("ldmatrix.sync.aligned.m8n8.x4.trans.shared.b16 {%0,%1,%2,%3}, [%4];"
                 : "=r"(r[0]), "=r"(r[1]), "=r"(r[2]), "=r"(r[3]) : "r"(addr));
}
__device__ __forceinline__ void mma_f16(float* d, const uint32_t* a, const uint32_t* b) {
    asm volatile(
        "mma.sync.aligned.m16n8k16.row.col.f32.f16.f16.f32 "
        "{%0,%1,%2,%3}, {%4,%5,%6,%7}, {%8,%9}, {%0,%1,%2,%3};"
        : "+f"(d[0]), "+f"(d[1]), "+f"(d[2]), "+f"(d[3])
        : "r"(a[0]), "r"(a[1]), "r"(a[2]), "r"(a[3]), "r"(b[0]), "r"(b[1]));
}
__device__ __forceinline__ uint2 h4pack(float x0, float x1, float x2, float x3) {
    const uint32_t u0 = __half_as_ushort(__float2half_rn(x0));
    const uint32_t u1 = __half_as_ushort(__float2half_rn(x1));
    const uint32_t u2 = __half_as_ushort(__float2half_rn(x2));
    const uint32_t u3 = __half_as_ushort(__float2half_rn(x3));
    return make_uint2((u1 << 16) | u0, (u3 << 16) | u2);
}

// ---------------------------------------------------------------------------
// Fused conversion: A-tile blocks do prescan (max-abs over the 64x64 tile)
// then masked fp32->fp16 convert (second pass re-reads via L1, no spills).
// Remaining blocks stream-convert B.
// ---------------------------------------------------------------------------
__global__ __launch_bounds__(256) void conv_all(const float* __restrict__ A,
                                                const float* __restrict__ B,
                                                __half* __restrict__ Ah,
                                                __half* __restrict__ Bh) {
    const int tid = threadIdx.x;
    if (blockIdx.x < A_TILE_BLOCKS) {
        const int tile = blockIdx.x;
        const int kt = tile & 31, mt = (tile >> 5) & 31, b = tile >> 10;
        const size_t tbase = ((size_t)b * MDIM + (size_t)mt * 64) * KDIM + (size_t)kt * 64;

        float mx = 0.0f;
#pragma unroll
        for (int i = 0; i < 4; i++) {
            const int q = i * 256 + tid;
            const int row = q >> 4, c4 = q & 15;
            const float4 v = *(const float4*)(A + tbase + (size_t)row * KDIM + c4 * 4);
            mx = fmaxf(mx, fmaxf(fmaxf(fabsf(v.x), fabsf(v.y)),
                                 fmaxf(fabsf(v.z), fabsf(v.w))));
        }
#pragma unroll
        for (int o = 16; o; o >>= 1) mx = fmaxf(mx, __shfl_xor_sync(0xffffffffu, mx, o));

        __shared__ float wmax[8];
        __shared__ float s_scale;
        if ((tid & 31) == 0) wmax[tid >> 5] = mx;
        __syncthreads();
        if (tid == 0) {
            float m = wmax[0];
#pragma unroll
            for (int i = 1; i < 8; i++) m = fmaxf(m, wmax[i]);
            s_scale = (m > 1e-6f) ? 1.0f : 0.0f;
        }
        __syncthreads();
        const float s = s_scale;

#pragma unroll
        for (int i = 0; i < 4; i++) {
            const int q = i * 256 + tid;
            const int row = q >> 4, c4 = q & 15;
            const size_t g = tbase + (size_t)row * KDIM + c4 * 4;
            const float4 v = *(const float4*)(A + g);   // L1 hit
            *(uint2*)(Ah + g) = h4pack(v.x * s, v.y * s, v.z * s, v.w * s);
        }
    } else {
        const size_t i4 = (size_t)(blockIdx.x - A_TILE_BLOCKS) * 256 + tid;
        const float4 v = ((const float4*)B)[i4];
        ((uint2*)Bh)[i4] = h4pack(v.x, v.y, v.z, v.w);
    }
}

// ---------------------------------------------------------------------------
// GEMM: fp16 mma.sync single product, 5-stage cp.async pipeline.
// 512 threads = 16 warps as 4(M) x 4(N); warp tile 64x32.
// ---------------------------------------------------------------------------
__global__ __launch_bounds__(512, 1) void gemm_mma(float* __restrict__ C) {
    extern __shared__ char smem[];
    const uint32_t sb = smem_u32(smem);
    const int tid = threadIdx.x;
    const int wid = tid >> 5, lane = tid & 31;
    const int b = blockIdx.z;
    const int bm = blockIdx.y * BM, bn = blockIdx.x * BN;

    const __half* pAh = g_Ah + (size_t)b * MDIM * KDIM;
    const __half* pBh = g_Bh + (size_t)b * KDIM * NDIM;

    // cp.async geometry (512 threads)
    const int ar = tid >> 2, ac = tid & 3;       // A: rows ar, ar+128; chunk ac
    const int bk = tid >> 4, bc = tid & 15;      // B: row bk; chunk bc
    const uint32_t saw = (uint32_t)(ar * 4 + (ac ^ ((ar >> 1) & 3))) * 16;  // +8192 for row+128
    const uint32_t sbw = (uint32_t)(bk * 16 + (bc ^ (bk & 7))) * 16;

    const __half* gAh0 = pAh + (size_t)(bm + ar) * KDIM + ac * 8;
    const __half* gBh0 = pBh + (size_t)bk * NDIM + bn + bc * 8;

    auto load_stage = [&](int t) {
        const uint32_t st = sb + (uint32_t)(t % STAGES) * STAGE_BYTES;
        const size_t aoff = (size_t)(t * BK);
        const size_t boff = (size_t)(t * BK) * NDIM;
        cpa16(st + saw,        gAh0 + aoff);
        cpa16(st + saw + 8192, gAh0 + aoff + (size_t)128 * KDIM);
        cpa16(st + A_ST_BYTES + sbw, gBh0 + boff);
    };

    // warp tiling: 4(M) x 4(N)
    const int wm = (wid >> 2) * 64;
    const int wn = (wid & 3) * 32;

    // ldmatrix lane geometry
    const int a_r = wm + (lane & 15);            // + i*16
    const int a_cL = (lane >> 4);                // + ks*2
    const int b_k = (lane & 15);                 // + ks*16
    const int b_cL = (wn >> 3) + (lane >> 4);    // + j2*2

    float acc[4][4][4];
#pragma unroll
    for (int i = 0; i < 4; i++)
#pragma unroll
        for (int j = 0; j < 4; j++)
#pragma unroll
            for (int q = 0; q < 4; q++) acc[i][j][q] = 0.0f;

    // prologue: stages 0..STAGES-2
#pragma unroll
    for (int t = 0; t < STAGES - 1; ++t) {
        load_stage(t);
        asm volatile("cp.async.commit_group;" ::: "memory");
    }

    for (int t = 0; t < NK; ++t) {
        asm volatile("cp.async.wait_group %0;" :: "n"(STAGES - 2) : "memory");
        __syncthreads();

        if (t + STAGES - 1 < NK) load_stage(t + STAGES - 1);
        asm volatile("cp.async.commit_group;" ::: "memory");

        const uint32_t st = sb + (uint32_t)(t % STAGES) * STAGE_BYTES;
        const uint32_t sAh = st;
        const uint32_t sBh = st + A_ST_BYTES;

#pragma unroll
        for (int ks = 0; ks < 2; ks++) {
            uint32_t ah[4][4], bh[2][4];
#pragma unroll
            for (int i = 0; i < 4; i++) {
                const int r = a_r + i * 16;
                const int c = ks * 2 + a_cL;
                const uint32_t off = (uint32_t)(r * 4 + (c ^ ((r >> 1) & 3))) * 16;
                ldsm_x4(ah[i], sAh + off);
            }
#pragma unroll
            for (int j2 = 0; j2 < 2; j2++) {
                const int k = ks * 16 + b_k;
                const int c = b_cL + j2 * 2;
                const uint32_t off = (uint32_t)(k * 16 + (c ^ (k & 7))) * 16;
                ldsm_x4_t(bh[j2], sBh + off);
            }
#pragma unroll
            for (int i = 0; i < 4; i++)
#pragma unroll
                for (int j2 = 0; j2 < 2; j2++)
#pragma unroll
                    for (int n8 = 0; n8 < 2; n8++)
                        mma_f16(acc[i][j2 * 2 + n8], ah[i], &bh[j2][n8 * 2]);
        }
        // stage reuse protected by next iteration's top-of-loop barrier
    }

    // epilogue
    float* Cb = C + (size_t)b * MDIM * NDIM;
    const int r0 = bm + wm + (lane >> 2);
    const int c0 = bn + wn + (lane & 3) * 2;
#pragma unroll
    for (int i = 0; i < 4; i++) {
#pragma unroll
        for (int j = 0; j < 4; j++) {
            const int row = r0 + i * 16;
            const int col = c0 + j * 8;
            *(float2*)&Cb[(size_t)row * NDIM + col] = make_float2(acc[i][j][0], acc[i][j][1]);
            *(float2*)&Cb[(size_t)(row + 8) * NDIM + col] = make_float2(acc[i][j][2], acc[i][j][3]);
        }
    }
}

extern "C" void kernel_launch(void* const* d_in, const int* in_sizes, int n_in,
                              void* d_out, int out_size) {
    const float* a = (const float*)d_in[0];
    const float* b = (const float*)d_in[1];
    float* out = (float*)d_out;

    __half *Ah, *Bh;
    cudaGetSymbolAddress((void**)&Ah, g_Ah);
    cudaGetSymbolAddress((void**)&Bh, g_Bh);

    conv_all<<<A_TILE_BLOCKS + B_CONV_BLOCKS, 256>>>(a, b, Ah, Bh);

    cudaFuncSetAttribute(gemm_mma, cudaFuncAttributeMaxDynamicSharedMemorySize, SMEM_TOTAL);
    dim3 grid(NDIM / BN, MDIM / BM, BATCH);
    gemm_mma<<<grid, 512, SMEM_TOTAL>>>(out);
}

// round 13
// speedup vs baseline: 3.5164x; 1.1149x over previous
#include <cuda_runtime.h>
#include <cuda_fp16.h>
#include <cstdint>

// SparseBMM: y[b,m,n] = sum_k A_masked[b,m,k] * B[b,k,n], fp32 [8,2048,2048].
// A_masked zeroes 64x64 tiles of A whose max-abs <= 1e-6.
// R13: single-product fp16 mma.sync; 256-thread CTAs (BM=BN=128), 5 stages
//      (80KB smem) -> 2 CTAs/SM by smem occupancy (no forced minctasm):
//      independent barrier domains fill the 43% tensor-idle seen in R11.

#define BATCH 8
#define MDIM 2048
#define NDIM 2048
#define KDIM 2048

#define BM 128
#define BN 128
#define BK 32
#define STAGES 5
#define NK (KDIM / BK)          // 64

#define A_ST_BYTES 8192         // 128 rows x 32 fp16 (64B/row)
#define B_ST_BYTES 8192         // 32 rows x 128 fp16 (256B/row)
#define STAGE_BYTES (A_ST_BYTES + B_ST_BYTES)   // 16384
#define SMEM_TOTAL (STAGES * STAGE_BYTES)       // 81920 -> 2 CTAs/SM

#define A_TILE_BLOCKS (BATCH * 32 * 32)                 // 8192
#define B_CONV_BLOCKS ((BATCH * KDIM * NDIM / 4) / 256) // 32768

__device__ __half g_Ah[(size_t)BATCH * MDIM * KDIM];
__device__ __half g_Bh[(size_t)BATCH * KDIM * NDIM];

// ---------------- helpers ----------------
__device__ __forceinline__ uint32_t smem_u32(const void* p) {
    uint32_t a;
    asm("{ .reg .u64 t; cvta.to.shared.u64 t, %1; cvt.u32.u64 %0, t; }" : "=r"(a) : "l"(p));
    return a;
}
__device__ __forceinline__ void cpa16(uint32_t dst, const void* src) {
    asm volatile("cp.async.cg.shared.global [%0], [%1], 16;" :: "r"(dst), "l"(src));
}
__device__ __forceinline__ void ldsm_x4(uint32_t* r, uint32_t addr) {
    asm volatile("ldmatrix.sync.aligned.m8n8.x4.shared.b16 {%0,%1,%2,%3}, [%4];"
                 : "=r"(r[0]), "=r"(r[1]), "=r"(r[2]), "=r"(r[3]) : "r"(addr));
}
__device__ __forceinline__ void ldsm_x4_t(uint32_t* r, uint32_t addr) {
    asm volatile("ldmatrix.sync.aligned.m8n8.x4.trans.shared.b16 {%0,%1,%2,%3}, [%4];"
                 : "=r"(r[0]), "=r"(r[1]), "=r"(r[2]), "=r"(r[3]) : "r"(addr));
}
__device__ __forceinline__ void mma_f16(float* d, const uint32_t* a, const uint32_t* b) {
    asm volatile(
        "mma.sync.aligned.m16n8k16.row.col.f32.f16.f16.f32 "
        "{%0,%1,%2,%3}, {%4,%5,%6,%7}, {%8,%9}, {%0,%1,%2,%3};"
        : "+f"(d[0]), "+f"(d[1]), "+f"(d[2]), "+f"(d[3])
        : "r"(a[0]), "r"(a[1]), "r"(a[2]), "r"(a[3]), "r"(b[0]), "r"(b[1]));
}
__device__ __forceinline__ uint2 h4pack(float x0, float x1, float x2, float x3) {
    const uint32_t u0 = __half_as_ushort(__float2half_rn(x0));
    const uint32_t u1 = __half_as_ushort(__float2half_rn(x1));
    const uint32_t u2 = __half_as_ushort(__float2half_rn(x2));
    const uint32_t u3 = __half_as_ushort(__float2half_rn(x3));
    return make_uint2((u1 << 16) | u0, (u3 << 16) | u2);
}

// ---------------------------------------------------------------------------
// Fused conversion: A-tile blocks do prescan (max-abs over the 64x64 tile)
// then masked fp32->fp16 convert (second pass re-reads via L1, no spills).
// Remaining blocks stream-convert B.
// ---------------------------------------------------------------------------
__global__ __launch_bounds__(256) void conv_all(const float* __restrict__ A,
                                                const float* __restrict__ B,
                                                __half* __restrict__ Ah,
                                                __half* __restrict__ Bh) {
    const int tid = threadIdx.x;
    if (blockIdx.x < A_TILE_BLOCKS) {
        const int tile = blockIdx.x;
        const int kt = tile & 31, mt = (tile >> 5) & 31, b = tile >> 10;
        const size_t tbase = ((size_t)b * MDIM + (size_t)mt * 64) * KDIM + (size_t)kt * 64;

        float mx = 0.0f;
#pragma unroll
        for (int i = 0; i < 4; i++) {
            const int q = i * 256 + tid;
            const int row = q >> 4, c4 = q & 15;
            const float4 v = *(const float4*)(A + tbase + (size_t)row * KDIM + c4 * 4);
            mx = fmaxf(mx, fmaxf(fmaxf(fabsf(v.x), fabsf(v.y)),
                                 fmaxf(fabsf(v.z), fabsf(v.w))));
        }
#pragma unroll
        for (int o = 16; o; o >>= 1) mx = fmaxf(mx, __shfl_xor_sync(0xffffffffu, mx, o));

        __shared__ float wmax[8];
        __shared__ float s_scale;
        if ((tid & 31) == 0) wmax[tid >> 5] = mx;
        __syncthreads();
        if (tid == 0) {
            float m = wmax[0];
#pragma unroll
            for (int i = 1; i < 8; i++) m = fmaxf(m, wmax[i]);
            s_scale = (m > 1e-6f) ? 1.0f : 0.0f;
        }
        __syncthreads();
        const float s = s_scale;

#pragma unroll
        for (int i = 0; i < 4; i++) {
            const int q = i * 256 + tid;
            const int row = q >> 4, c4 = q & 15;
            const size_t g = tbase + (size_t)row * KDIM + c4 * 4;
            const float4 v = *(const float4*)(A + g);   // L1 hit
            *(uint2*)(Ah + g) = h4pack(v.x * s, v.y * s, v.z * s, v.w * s);
        }
    } else {
        const size_t i4 = (size_t)(blockIdx.x - A_TILE_BLOCKS) * 256 + tid;
        const float4 v = ((const float4*)B)[i4];
        ((uint2*)Bh)[i4] = h4pack(v.x, v.y, v.z, v.w);
    }
}

// ---------------------------------------------------------------------------
// GEMM: fp16 mma.sync single product, 5-stage cp.async pipeline.
// 256 threads = 8 warps as 2(M) x 4(N); warp tile 64x32.
// 80KB smem/CTA -> 2 CTAs co-resident per SM.
// ---------------------------------------------------------------------------
__global__ __launch_bounds__(256) void gemm_mma(float* __restrict__ C) {
    extern __shared__ char smem[];
    const uint32_t sb = smem_u32(smem);
    const int tid = threadIdx.x;
    const int wid = tid >> 5, lane = tid & 31;
    const int b = blockIdx.z;
    const int bm = blockIdx.y * BM, bn = blockIdx.x * BN;

    const __half* pAh = g_Ah + (size_t)b * MDIM * KDIM;
    const __half* pBh = g_Bh + (size_t)b * KDIM * NDIM;

    // cp.async geometry (256 threads)
    // A: 128 rows x 4 chunks(16B); rows ar, ar+64. 512 chunks, 2/thread.
    const int ar = tid >> 2, ac = tid & 3;
    // B: 32 rows x 16 chunks; chunks bc, bc+8. 512 chunks, 2/thread.
    const int bk = tid >> 3, bc = tid & 7;
    const uint32_t saw = (uint32_t)(ar * 4 + (ac ^ ((ar >> 1) & 3))) * 16;  // +4096 for row+64
    const uint32_t sbw = (uint32_t)(bk * 16 + (bc ^ (bk & 7))) * 16;        // +128 for chunk+8

    const __half* gAh0 = pAh + (size_t)(bm + ar) * KDIM + ac * 8;
    const __half* gBh0 = pBh + (size_t)bk * NDIM + bn + bc * 8;

    auto load_stage = [&](int t) {
        const uint32_t st = sb + (uint32_t)(t % STAGES) * STAGE_BYTES;
        const size_t aoff = (size_t)(t * BK);
        const size_t boff = (size_t)(t * BK) * NDIM;
        cpa16(st + saw,        gAh0 + aoff);
        cpa16(st + saw + 4096, gAh0 + aoff + (size_t)64 * KDIM);
        const uint32_t sB = st + A_ST_BYTES;
        cpa16(sB + sbw,        gBh0 + boff);
        cpa16(sB + sbw + 128,  gBh0 + boff + 64);
    };

    // warp tiling: 2(M) x 4(N)
    const int wm = (wid >> 2) * 64;      // 0 or 64
    const int wn = (wid & 3) * 32;       // 0,32,64,96

    // ldmatrix lane geometry
    const int a_r = wm + (lane & 15);            // + i*16
    const int a_cL = (lane >> 4);                // + ks*2
    const int b_k = (lane & 15);                 // + ks*16
    const int b_cL = (wn >> 3) + (lane >> 4);    // + j2*2

    float acc[4][4][4];
#pragma unroll
    for (int i = 0; i < 4; i++)
#pragma unroll
        for (int j = 0; j < 4; j++)
#pragma unroll
            for (int q = 0; q < 4; q++) acc[i][j][q] = 0.0f;

    // prologue: stages 0..STAGES-2
#pragma unroll
    for (int t = 0; t < STAGES - 1; ++t) {
        load_stage(t);
        asm volatile("cp.async.commit_group;" ::: "memory");
    }

    for (int t = 0; t < NK; ++t) {
        asm volatile("cp.async.wait_group %0;" :: "n"(STAGES - 2) : "memory");
        __syncthreads();

        if (t + STAGES - 1 < NK) load_stage(t + STAGES - 1);
        asm volatile("cp.async.commit_group;" ::: "memory");

        const uint32_t st = sb + (uint32_t)(t % STAGES) * STAGE_BYTES;
        const uint32_t sAh = st;
        const uint32_t sBh = st + A_ST_BYTES;

#pragma unroll
        for (int ks = 0; ks < 2; ks++) {
            uint32_t ah[4][4], bh[2][4];
#pragma unroll
            for (int i = 0; i < 4; i++) {
                const int r = a_r + i * 16;
                const int c = ks * 2 + a_cL;
                const uint32_t off = (uint32_t)(r * 4 + (c ^ ((r >> 1) & 3))) * 16;
                ldsm_x4(ah[i], sAh + off);
            }
#pragma unroll
            for (int j2 = 0; j2 < 2; j2++) {
                const int k = ks * 16 + b_k;
                const int c = b_cL + j2 * 2;
                const uint32_t off = (uint32_t)(k * 16 + (c ^ (k & 7))) * 16;
                ldsm_x4_t(bh[j2], sBh + off);
            }
#pragma unroll
            for (int i = 0; i < 4; i++)
#pragma unroll
                for (int j2 = 0; j2 < 2; j2++)
#pragma unroll
                    for (int n8 = 0; n8 < 2; n8++)
                        mma_f16(acc[i][j2 * 2 + n8], ah[i], &bh[j2][n8 * 2]);
        }
        // stage reuse protected by next iteration's top-of-loop barrier
    }

    // epilogue
    float* Cb = C + (size_t)b * MDIM * NDIM;
    const int r0 = bm + wm + (lane >> 2);
    const int c0 = bn + wn + (lane & 3) * 2;
#pragma unroll
    for (int i = 0; i < 4; i++) {
#pragma unroll
        for (int j = 0; j < 4; j++) {
            const int row = r0 + i * 16;
            const int col = c0 + j * 8;
            *(float2*)&Cb[(size_t)row * NDIM + col] = make_float2(acc[i][j][0], acc[i][j][1]);
            *(float2*)&Cb[(size_t)(row + 8) * NDIM + col] = make_float2(acc[i][j][2], acc[i][j][3]);
        }
    }
}

extern "C" void kernel_launch(void* const* d_in, const int* in_sizes, int n_in,
                              void* d_out, int out_size) {
    const float* a = (const float*)d_in[0];
    const float* b = (const float*)d_in[1];
    float* out = (float*)d_out;

    __half *Ah, *Bh;
    cudaGetSymbolAddress((void**)&Ah, g_Ah);
    cudaGetSymbolAddress((void**)&Bh, g_Bh);

    conv_all<<<A_TILE_BLOCKS + B_CONV_BLOCKS, 256>>>(a, b, Ah, Bh);

    cudaFuncSetAttribute(gemm_mma, cudaFuncAttributeMaxDynamicSharedMemorySize, SMEM_TOTAL);
    dim3 grid(NDIM / BN, MDIM / BM, BATCH);
    gemm_mma<<<grid, 256, SMEM_TOTAL>>>(out);
}

// round 14
// speedup vs baseline: 4.1804x; 1.1888x over previous
#include <cuda_runtime.h>
#include <cuda_fp16.h>
#include <cstdint>

// SparseBMM: y[b,m,n] = sum_k A_masked[b,m,k] * B[b,k,n], fp32 [8,2048,2048].
// A_masked zeroes 64x64 tiles of A whose max-abs <= 1e-6.
// R14: fp16 single-product mma.sync; 128-thread CTAs, block 128x128,
//      4 warps as 2x2 (warp tile 64x64): MMA:ldsm ratio 2.67 -> 4.0.
//      5 stages (80KB) -> 2 CTAs/SM. Hoisted ldsm offsets.

#define BATCH 8
#define MDIM 2048
#define NDIM 2048
#define KDIM 2048

#define BM 128
#define BN 128
#define BK 32
#define STAGES 5
#define NK (KDIM / BK)          // 64

#define A_ST_BYTES 8192         // 128 rows x 32 fp16 (64B/row)
#define B_ST_BYTES 8192         // 32 rows x 128 fp16 (256B/row)
#define STAGE_BYTES (A_ST_BYTES + B_ST_BYTES)   // 16384
#define SMEM_TOTAL (STAGES * STAGE_BYTES)       // 81920 -> 2 CTAs/SM

#define A_TILE_BLOCKS (BATCH * 32 * 32)                 // 8192
#define B_CONV_BLOCKS ((BATCH * KDIM * NDIM / 4) / 256) // 32768

__device__ __half g_Ah[(size_t)BATCH * MDIM * KDIM];
__device__ __half g_Bh[(size_t)BATCH * KDIM * NDIM];

// ---------------- helpers ----------------
__device__ __forceinline__ uint32_t smem_u32(const void* p) {
    uint32_t a;
    asm("{ .reg .u64 t; cvta.to.shared.u64 t, %1; cvt.u32.u64 %0, t; }" : "=r"(a) : "l"(p));
    return a;
}
__device__ __forceinline__ void cpa16(uint32_t dst, const void* src) {
    asm volatile("cp.async.cg.shared.global [%0], [%1], 16;" :: "r"(dst), "l"(src));
}
__device__ __forceinline__ void ldsm_x4(uint32_t* r, uint32_t addr) {
    asm volatile("ldmatrix.sync.aligned.m8n8.x4.shared.b16 {%0,%1,%2,%3}, [%4];"
                 : "=r"(r[0]), "=r"(r[1]), "=r"(r[2]), "=r"(r[3]) : "r"(addr));
}
__device__ __forceinline__ void ldsm_x4_t(uint32_t* r, uint32_t addr) {
    asm volatile("ldmatrix.sync.aligned.m8n8.x4.trans.shared.b16 {%0,%1,%2,%3}, [%4];"
                 : "=r"(r[0]), "=r"(r[1]), "=r"(r[2]), "=r"(r[3]) : "r"(addr));
}
__device__ __forceinline__ void mma_f16(float* d, const uint32_t* a, const uint32_t* b) {
    asm volatile(
        "mma.sync.aligned.m16n8k16.row.col.f32.f16.f16.f32 "
        "{%0,%1,%2,%3}, {%4,%5,%6,%7}, {%8,%9}, {%0,%1,%2,%3};"
        : "+f"(d[0]), "+f"(d[1]), "+f"(d[2]), "+f"(d[3])
        : "r"(a[0]), "r"(a[1]), "r"(a[2]), "r"(a[3]), "r"(b[0]), "r"(b[1]));
}
__device__ __forceinline__ uint2 h4pack(float x0, float x1, float x2, float x3) {
    const uint32_t u0 = __half_as_ushort(__float2half_rn(x0));
    const uint32_t u1 = __half_as_ushort(__float2half_rn(x1));
    const uint32_t u2 = __half_as_ushort(__float2half_rn(x2));
    const uint32_t u3 = __half_as_ushort(__float2half_rn(x3));
    return make_uint2((u1 << 16) | u0, (u3 << 16) | u2);
}

// ---------------------------------------------------------------------------
// Fused conversion (unchanged from R13).
// ---------------------------------------------------------------------------
__global__ __launch_bounds__(256) void conv_all(const float* __restrict__ A,
                                                const float* __restrict__ B,
                                                __half* __restrict__ Ah,
                                                __half* __restrict__ Bh) {
    const int tid = threadIdx.x;
    if (blockIdx.x < A_TILE_BLOCKS) {
        const int tile = blockIdx.x;
        const int kt = tile & 31, mt = (tile >> 5) & 31, b = tile >> 10;
        const size_t tbase = ((size_t)b * MDIM + (size_t)mt * 64) * KDIM + (size_t)kt * 64;

        float mx = 0.0f;
#pragma unroll
        for (int i = 0; i < 4; i++) {
            const int q = i * 256 + tid;
            const int row = q >> 4, c4 = q & 15;
            const float4 v = *(const float4*)(A + tbase + (size_t)row * KDIM + c4 * 4);
            mx = fmaxf(mx, fmaxf(fmaxf(fabsf(v.x), fabsf(v.y)),
                                 fmaxf(fabsf(v.z), fabsf(v.w))));
        }
#pragma unroll
        for (int o = 16; o; o >>= 1) mx = fmaxf(mx, __shfl_xor_sync(0xffffffffu, mx, o));

        __shared__ float wmax[8];
        __shared__ float s_scale;
        if ((tid & 31) == 0) wmax[tid >> 5] = mx;
        __syncthreads();
        if (tid == 0) {
            float m = wmax[0];
#pragma unroll
            for (int i = 1; i < 8; i++) m = fmaxf(m, wmax[i]);
            s_scale = (m > 1e-6f) ? 1.0f : 0.0f;
        }
        __syncthreads();
        const float s = s_scale;

#pragma unroll
        for (int i = 0; i < 4; i++) {
            const int q = i * 256 + tid;
            const int row = q >> 4, c4 = q & 15;
            const size_t g = tbase + (size_t)row * KDIM + c4 * 4;
            const float4 v = *(const float4*)(A + g);   // L1 hit
            *(uint2*)(Ah + g) = h4pack(v.x * s, v.y * s, v.z * s, v.w * s);
        }
    } else {
        const size_t i4 = (size_t)(blockIdx.x - A_TILE_BLOCKS) * 256 + tid;
        const float4 v = ((const float4*)B)[i4];
        ((uint2*)Bh)[i4] = h4pack(v.x, v.y, v.z, v.w);
    }
}

// ---------------------------------------------------------------------------
// GEMM: fp16 mma.sync single product, 5-stage cp.async pipeline.
// 128 threads = 4 warps as 2(M) x 2(N); warp tile 64x64. 2 CTAs/SM.
// ---------------------------------------------------------------------------
__global__ __launch_bounds__(128) void gemm_mma(float* __restrict__ C) {
    extern __shared__ char smem[];
    const uint32_t sb = smem_u32(smem);
    const int tid = threadIdx.x;
    const int wid = tid >> 5, lane = tid & 31;
    const int b = blockIdx.z;
    const int bm = blockIdx.y * BM, bn = blockIdx.x * BN;

    const __half* pAh = g_Ah + (size_t)b * MDIM * KDIM;
    const __half* pBh = g_Bh + (size_t)b * KDIM * NDIM;

    // cp.async geometry (128 threads, 4 chunks each for A and B)
    // A: 128 rows x 4 chunks(16B): idx = i*128+tid, r = idx>>2, c = idx&3
    // B: 32 rows x 16 chunks:      idx = i*128+tid, k = idx>>4, c = idx&15
    uint32_t a_sw[4], b_sw[4];
    size_t a_go[4], b_go[4];
#pragma unroll
    for (int i = 0; i < 4; i++) {
        const int ia = i * 128 + tid;
        const int r = ia >> 2, c = ia & 3;
        a_sw[i] = (uint32_t)(r * 4 + (c ^ ((r >> 1) & 3))) * 16;
        a_go[i] = (size_t)(bm + r) * KDIM + c * 8;
        const int k = ia >> 4, cc = ia & 15;
        b_sw[i] = (uint32_t)(k * 16 + (cc ^ (k & 7))) * 16;
        b_go[i] = (size_t)k * NDIM + bn + cc * 8;
    }

    auto load_stage = [&](int t) {
        const uint32_t st = sb + (uint32_t)(t % STAGES) * STAGE_BYTES;
        const size_t aoff = (size_t)(t * BK);
        const size_t boff = (size_t)(t * BK) * NDIM;
#pragma unroll
        for (int i = 0; i < 4; i++) {
            cpa16(st + a_sw[i], pAh + a_go[i] + aoff);
            cpa16(st + A_ST_BYTES + b_sw[i], pBh + b_go[i] + boff);
        }
    };

    // warp tiling: 2(M) x 2(N); warp tile 64x64
    const int wm = (wid >> 1) * 64;      // 0 or 64
    const int wn = (wid & 1) * 64;       // 0 or 64

    // hoisted ldsm offsets (relative to stage base)
    const int a_r = wm + (lane & 15);
    const int a_cL = (lane >> 4);
    const int b_k = (lane & 15);
    const int b_cL = (wn >> 3) + (lane >> 4);
    uint32_t a_off[2][4], b_off[2][4];
#pragma unroll
    for (int ks = 0; ks < 2; ks++) {
#pragma unroll
        for (int i = 0; i < 4; i++) {
            const int r = a_r + i * 16;
            const int c = ks * 2 + a_cL;
            a_off[ks][i] = (uint32_t)(r * 4 + (c ^ ((r >> 1) & 3))) * 16;
        }
#pragma unroll
        for (int j2 = 0; j2 < 4; j2++) {
            const int k = ks * 16 + b_k;
            const int c = b_cL + j2 * 2;
            b_off[ks][j2] = A_ST_BYTES + (uint32_t)(k * 16 + (c ^ (k & 7))) * 16;
        }
    }

    float acc[4][8][4];
#pragma unroll
    for (int i = 0; i < 4; i++)
#pragma unroll
        for (int j = 0; j < 8; j++)
#pragma unroll
            for (int q = 0; q < 4; q++) acc[i][j][q] = 0.0f;

    // prologue: stages 0..STAGES-2
#pragma unroll
    for (int t = 0; t < STAGES - 1; ++t) {
        load_stage(t);
        asm volatile("cp.async.commit_group;" ::: "memory");
    }

    for (int t = 0; t < NK; ++t) {
        asm volatile("cp.async.wait_group %0;" :: "n"(STAGES - 2) : "memory");
        __syncthreads();

        if (t + STAGES - 1 < NK) load_stage(t + STAGES - 1);
        asm volatile("cp.async.commit_group;" ::: "memory");

        const uint32_t st = sb + (uint32_t)(t % STAGES) * STAGE_BYTES;

#pragma unroll
        for (int ks = 0; ks < 2; ks++) {
            uint32_t ah[4][4], bh[4][4];
#pragma unroll
            for (int i = 0; i < 4; i++) ldsm_x4(ah[i], st + a_off[ks][i]);
#pragma unroll
            for (int j2 = 0; j2 < 4; j2++) ldsm_x4_t(bh[j2], st + b_off[ks][j2]);
#pragma unroll
            for (int i = 0; i < 4; i++)
#pragma unroll
                for (int j2 = 0; j2 < 4; j2++)
#pragma unroll
                    for (int n8 = 0; n8 < 2; n8++)
                        mma_f16(acc[i][j2 * 2 + n8], ah[i], &bh[j2][n8 * 2]);
        }
        // stage reuse protected by next iteration's top-of-loop barrier
    }

    // epilogue
    float* Cb = C + (size_t)b * MDIM * NDIM;
    const int r0 = bm + wm + (lane >> 2);
    const int c0 = bn + wn + (lane & 3) * 2;
#pragma unroll
    for (int i = 0; i < 4; i++) {
#pragma unroll
        for (int j = 0; j < 8; j++) {
            const int row = r0 + i * 16;
            const int col = c0 + j * 8;
            *(float2*)&Cb[(size_t)row * NDIM + col] = make_float2(acc[i][j][0], acc[i][j][1]);
            *(float2*)&Cb[(size_t)(row + 8) * NDIM + col] = make_float2(acc[i][j][2], acc[i][j][3]);
        }
    }
}

extern "C" void kernel_launch(void* const* d_in, const int* in_sizes, int n_in,
                              void* d_out, int out_size) {
    const float* a = (const float*)d_in[0];
    const float* b = (const float*)d_in[1];
    float* out = (float*)d_out;

    __half *Ah, *Bh;
    cudaGetSymbolAddress((void**)&Ah, g_Ah);
    cudaGetSymbolAddress((void**)&Bh, g_Bh);

    conv_all<<<A_TILE_BLOCKS + B_CONV_BLOCKS, 256>>>(a, b, Ah, Bh);

    cudaFuncSetAttribute(gemm_mma, cudaFuncAttributeMaxDynamicSharedMemorySize, SMEM_TOTAL);
    dim3 grid(NDIM / BN, MDIM / BM, BATCH);
    gemm_mma<<<grid, 128, SMEM_TOTAL>>>(out);
}